// round 13
// baseline (speedup 1.0000x reference)
#include <cuda_runtime.h>
#include <cuda_fp16.h>
#include <math.h>
#include <cstdint>

#define SQ    2048
#define HID   4096
#define NH    32
#define NKV   8
#define HD    128
#define QDIM  (NH*HD)    // 4096
#define KVDIM (NKV*HD)   // 1024
#define QKVD  (QDIM + 2*KVDIM)   // 6144

// ---------------- scratch (static device allocations) ----------------
__device__ __half g_Ah [SQ * HID];
__device__ __half g_AOh[SQ * QDIM];

__device__ __half g_Qh[SQ * QDIM];
__device__ __half g_Kh[SQ * KVDIM];
__device__ __half g_Vh[SQ * KVDIM];

__device__ __half g_Wqkv[HID * QKVD];   // [K=4096, N=6144] natural layout, fp16
__device__ __half g_Wo16[HID * QDIM];   // [K=4096, N=4096] natural layout, fp16

__device__ float g_cs[SQ * 64];         // rope cos table
__device__ float g_sn[SQ * 64];         // rope sin table

// ---------------- PTX helpers (sm_80-era instructions only) ----------------
__device__ __forceinline__ uint32_t smem_u32(const void* p) {
    uint32_t a;
    asm("{ .reg .u64 t; cvta.to.shared.u64 t, %1; cvt.u32.u64 %0, t; }" : "=r"(a) : "l"(p));
    return a;
}

__device__ __forceinline__ void cpa16(uint32_t dst, const void* src) {
    asm volatile("cp.async.cg.shared.global [%0], [%1], 16;" :: "r"(dst), "l"(src) : "memory");
}
#define CP_COMMIT() asm volatile("cp.async.commit_group;" ::: "memory")
#define CP_WAIT2()  asm volatile("cp.async.wait_group 2;" ::: "memory")
#define CP_WAIT1()  asm volatile("cp.async.wait_group 1;" ::: "memory")
#define CP_WAIT0()  asm volatile("cp.async.wait_group 0;" ::: "memory")

__device__ __forceinline__ void ldsm_x4(uint32_t& r0, uint32_t& r1, uint32_t& r2, uint32_t& r3,
                                        uint32_t addr) {
    asm volatile("ldmatrix.sync.aligned.m8n8.x4.shared.b16 {%0,%1,%2,%3}, [%4];"
                 : "=r"(r0), "=r"(r1), "=r"(r2), "=r"(r3) : "r"(addr));
}
__device__ __forceinline__ void ldsm_x4_t(uint32_t& r0, uint32_t& r1, uint32_t& r2, uint32_t& r3,
                                          uint32_t addr) {
    asm volatile("ldmatrix.sync.aligned.m8n8.x4.trans.shared.b16 {%0,%1,%2,%3}, [%4];"
                 : "=r"(r0), "=r"(r1), "=r"(r2), "=r"(r3) : "r"(addr));
}

__device__ __forceinline__ void mma_f16(float& d0, float& d1, float& d2, float& d3,
                                        uint32_t a0, uint32_t a1, uint32_t a2, uint32_t a3,
                                        uint32_t b0, uint32_t b1) {
    asm volatile("mma.sync.aligned.m16n8k16.row.col.f32.f16.f16.f32 "
                 "{%0,%1,%2,%3}, {%4,%5,%6,%7}, {%8,%9}, {%0,%1,%2,%3};"
                 : "+f"(d0), "+f"(d1), "+f"(d2), "+f"(d3)
                 : "r"(a0), "r"(a1), "r"(a2), "r"(a3), "r"(b0), "r"(b1));
}

__device__ __forceinline__ uint32_t pack2h(float a, float b) {
    __half2 h;
    h.x = __float2half_rn(a);
    h.y = __float2half_rn(b);
    return *(uint32_t*)&h;
}

// ---------------- fused prep: hs convert + 4 weight converts + rope table ----------------
__global__ __launch_bounds__(256) void conv_fused(
    const float* __restrict__ hs,
    const float* __restrict__ Wq, const float* __restrict__ Wk,
    const float* __restrict__ Wv, const float* __restrict__ Wo,
    const int* __restrict__ pos_ids,
    __half* __restrict__ ah, __half* __restrict__ wqkv, __half* __restrict__ wo16,
    float* __restrict__ cs_tab, float* __restrict__ sn_tab)
{
    int b = blockIdx.x;
    if (b >= 24576) {
        int idx = (b - 24576) * 256 + threadIdx.x;
        int s = idx >> 6, i = idx & 63;
        double invf = exp(-(double)i * (9.210340371976184 / 64.0));
        float ang = (float)((double)pos_ids[s] * invf);
        float c, si;
        sincosf(ang, &si, &c);
        cs_tab[idx] = c;
        sn_tab[idx] = si;
        return;
    }
    if (b < 4096) {
        int i = b * 256 + threadIdx.x;
        float4 a = ((const float4*)hs)[2 * i];
        float4 c = ((const float4*)hs)[2 * i + 1];
        uint4 o;
        o.x = pack2h(a.x, a.y);
        o.y = pack2h(a.z, a.w);
        o.z = pack2h(c.x, c.y);
        o.w = pack2h(c.z, c.w);
        ((uint4*)ah)[i] = o;
        return;
    }
    b -= 4096;
    const float* W; __half* D; int nq, coff, stride;
    if (b < 8192)        { W = Wq; D = wqkv; nq = 4096 / 8; coff = 0;    stride = QKVD; }
    else if (b < 10240)  { b -= 8192;  W = Wk; D = wqkv; nq = 1024 / 8; coff = 4096; stride = QKVD; }
    else if (b < 12288)  { b -= 10240; W = Wv; D = wqkv; nq = 1024 / 8; coff = 5120; stride = QKVD; }
    else                 { b -= 12288; W = Wo; D = wo16; nq = 4096 / 8; coff = 0;    stride = 4096; }

    int idx = b * 256 + threadIdx.x;
    int k = idx / nq, nc = (idx - k * nq) << 3;
    const float* src = W + (size_t)k * (nq << 3) + nc;
    float4 a = *(const float4*)src;
    float4 c = *(const float4*)(src + 4);
    uint4 o;
    o.x = pack2h(a.x, a.y);
    o.y = pack2h(a.z, a.w);
    o.z = pack2h(c.x, c.y);
    o.w = pack2h(c.z, c.w);
    *(uint4*)(D + (size_t)k * stride + coff + nc) = o;
}

// ---------------- HMMA fp16 GEMM (fragment-pipelined mainloop) ----------------
// C[M,N] fp32 = A[M,K] @ B[K,N]. CTA 128x256, 8 warps 2(m) x 4(n), k-chunk 64,
// 4-stage cp.async, trans-ldsm for B, ks-level fragment double-buffering.
// EPI==0: plain fp32 C store. EPI==1: fused RoPE/convert epilogue -> Qh/Kh/Vh fp16.
#define SWZ64(r, c8) ((r) * 128 + (((c8) ^ ((r) & 7)) << 4))
#define SWZB(r, g)   ((r) * 512 + (((g) ^ ((r) & 7)) << 4))

template <int EPI>
__global__ __launch_bounds__(256, 1) void gemm_hmma(
    const __half* __restrict__ A, const __half* __restrict__ B,
    float* __restrict__ C,
    __half* __restrict__ Qh, __half* __restrict__ Kh, __half* __restrict__ Vh,
    const float* __restrict__ cs_tab, const float* __restrict__ sn_tab,
    int M, int N, int K)
{
    extern __shared__ char smem[];
    constexpr int TILE_A = 128 * 64 * 2;    // 16 KB
    constexpr int TILE_B = 64 * 256 * 2;    // 32 KB
    constexpr int STAGE  = TILE_A + TILE_B; // 48 KB
    const uint32_t sb = smem_u32(smem);

    const int tid  = threadIdx.x;
    const int wid  = tid >> 5;
    const int lane = tid & 31;
    const int m0 = blockIdx.y * 128;
    const int n0 = blockIdx.x * 256;
    const int wm = (wid >> 2) * 64;
    const int wn = (wid & 3) * 64;
    const int nk = K >> 6;

    const int rl  = lane & 15;
    const int ch  = lane >> 4;

    float acc[4][8][4];
#pragma unroll
    for (int i = 0; i < 4; ++i)
#pragma unroll
        for (int j = 0; j < 8; ++j)
#pragma unroll
            for (int q = 0; q < 4; ++q) acc[i][j][q] = 0.f;

    auto load_stage = [&](int c, int s) {
        const int kb = c * 64;
        const uint32_t st = sb + s * STAGE;
#pragma unroll
        for (int i = 0; i < 4; ++i) {
            int id = tid + i * 256;
            int r = id >> 3, c8 = id & 7;
            cpa16(st + SWZ64(r, c8), A + (size_t)(m0 + r) * K + kb + c8 * 8);
        }
#pragma unroll
        for (int i = 0; i < 8; ++i) {
            int id = tid + i * 256;
            int r = id >> 5, g = id & 31;
            cpa16(st + TILE_A + SWZB(r, g), B + (size_t)(kb + r) * N + n0 + g * 8);
        }
        CP_COMMIT();
    };

    load_stage(0, 0);
    if (nk > 1) load_stage(1, 1);
    if (nk > 2) load_stage(2, 2);

    for (int c = 0; c < nk; ++c) {
        if (c + 2 < nk)      { CP_WAIT2(); }
        else if (c + 1 < nk) { CP_WAIT1(); }
        else                 { CP_WAIT0(); }
        __syncthreads();
        if (c + 3 < nk) load_stage(c + 3, (c + 3) & 3);

        const uint32_t st = sb + (c & 3) * STAGE;
        const uint32_t stb = st + TILE_A;
        const int gb0 = wn >> 3;

        uint32_t af[2][4][4], bf[2][4][4];
        // preload ks = 0 fragments
#pragma unroll
        for (int mt = 0; mt < 4; ++mt)
            ldsm_x4(af[0][mt][0], af[0][mt][1], af[0][mt][2], af[0][mt][3],
                    st + SWZ64(wm + mt * 16 + rl, ch));
#pragma unroll
        for (int np = 0; np < 4; ++np)
            ldsm_x4_t(bf[0][np][0], bf[0][np][1], bf[0][np][2], bf[0][np][3],
                      stb + SWZB(rl, gb0 + np * 2 + ch));

#pragma unroll
        for (int ks = 0; ks < 4; ++ks) {
            const int cur = ks & 1, nxt = cur ^ 1;
            if (ks < 3) {
                // prefetch ks+1 fragments while this ks's MMAs run
#pragma unroll
                for (int mt = 0; mt < 4; ++mt)
                    ldsm_x4(af[nxt][mt][0], af[nxt][mt][1], af[nxt][mt][2], af[nxt][mt][3],
                            st + SWZ64(wm + mt * 16 + rl, 2 * (ks + 1) + ch));
#pragma unroll
                for (int np = 0; np < 4; ++np)
                    ldsm_x4_t(bf[nxt][np][0], bf[nxt][np][1], bf[nxt][np][2], bf[nxt][np][3],
                              stb + SWZB((ks + 1) * 16 + rl, gb0 + np * 2 + ch));
            }
#pragma unroll
            for (int np = 0; np < 4; ++np) {
#pragma unroll
                for (int mt = 0; mt < 4; ++mt) {
                    float* d0 = acc[mt][np * 2];
                    float* d1 = acc[mt][np * 2 + 1];
                    mma_f16(d0[0], d0[1], d0[2], d0[3],
                            af[cur][mt][0], af[cur][mt][1], af[cur][mt][2], af[cur][mt][3],
                            bf[cur][np][0], bf[cur][np][1]);
                    mma_f16(d1[0], d1[1], d1[2], d1[3],
                            af[cur][mt][0], af[cur][mt][1], af[cur][mt][2], af[cur][mt][3],
                            bf[cur][np][2], bf[cur][np][3]);
                }
            }
        }
    }

    if (EPI == 0) {
#pragma unroll
        for (int mt = 0; mt < 4; ++mt) {
#pragma unroll
            for (int nt = 0; nt < 8; ++nt) {
                int rg = m0 + wm + mt * 16 + (lane >> 2);
                int cg = n0 + wn + nt * 8 + (lane & 3) * 2;
                float* d = acc[mt][nt];
                *(float2*)(C + (size_t)rg * N + cg)       = make_float2(d[0], d[1]);
                *(float2*)(C + (size_t)(rg + 8) * N + cg) = make_float2(d[2], d[3]);
            }
        }
    } else {
        // fused QKV epilogue: stage acc to smem (fp32), then RoPE/convert -> fp16.
        __syncthreads();
        float* sf = (float*)smem;
        constexpr int RS = 264;
#pragma unroll
        for (int mt = 0; mt < 4; ++mt) {
#pragma unroll
            for (int nt = 0; nt < 8; ++nt) {
                int rl_ = wm + mt * 16 + (lane >> 2);
                int cl_ = wn + nt * 8 + (lane & 3) * 2;
                float* d = acc[mt][nt];
                *(float2*)(sf + rl_ * RS + cl_)       = make_float2(d[0], d[1]);
                *(float2*)(sf + (rl_ + 8) * RS + cl_) = make_float2(d[2], d[3]);
            }
        }
        __syncthreads();

        const float qscale = 0.08838834764831845f;
        const int qd = tid & 31;
        const int head_l = qd >> 4, q4 = (qd & 15) << 2;
        const int rbase = (tid >> 5) << 4;
        const int colbase = head_l * 128 + q4;
        const bool isQ = (n0 < QDIM);
        const bool isK = (n0 >= QDIM) && (n0 < QDIM + KVDIM);

#pragma unroll 4
        for (int rr = 0; rr < 16; ++rr) {
            int row = rbase + rr;
            int grow = m0 + row;
            const float* bp = sf + row * RS + colbase;
            float4 x0 = *(const float4*)bp;
            float4 x1 = *(const float4*)(bp + 64);
            uint2 lo, hi;
            if (isQ || isK) {
                float4 c4 = *(const float4*)(cs_tab + (size_t)grow * 64 + q4);
                float4 s4 = *(const float4*)(sn_tab + (size_t)grow * 64 + q4);
                if (isQ) {
                    lo.x = pack2h((x0.x * c4.x - x1.x * s4.x) * qscale,
                                  (x0.y * c4.y - x1.y * s4.y) * qscale);
                    lo.y = pack2h((x0.z * c4.z - x1.z * s4.z) * qscale,
                                  (x0.w * c4.w - x1.w * s4.w) * qscale);
                    hi.x = pack2h((x1.x * c4.x + x0.x * s4.x) * qscale,
                                  (x1.y * c4.y + x0.y * s4.y) * qscale);
                    hi.y = pack2h((x1.z * c4.z + x0.z * s4.z) * qscale,
                                  (x1.w * c4.w + x0.w * s4.w) * qscale);
                } else {
                    lo.x = pack2h(x0.x * c4.x - x1.x * s4.x, x0.y * c4.y - x1.y * s4.y);
                    lo.y = pack2h(x0.z * c4.z - x1.z * s4.z, x0.w * c4.w - x1.w * s4.w);
                    hi.x = pack2h(x1.x * c4.x + x0.x * s4.x, x1.y * c4.y + x0.y * s4.y);
                    hi.y = pack2h(x1.z * c4.z + x0.z * s4.z, x1.w * c4.w + x0.w * s4.w);
                }
            } else {
                lo.x = pack2h(x0.x, x0.y); lo.y = pack2h(x0.z, x0.w);
                hi.x = pack2h(x1.x, x1.y); hi.y = pack2h(x1.z, x1.w);
            }
            __half* dst;
            if (isQ)      dst = Qh + (size_t)grow * QDIM + n0 + colbase;
            else if (isK) dst = Kh + (size_t)grow * KVDIM + (n0 - QDIM) + colbase;
            else          dst = Vh + (size_t)grow * KVDIM + (n0 - QDIM - KVDIM) + colbase;
            *(uint2*)dst        = lo;
            *(uint2*)(dst + 64) = hi;
        }
    }
}

// ---------------- HMMA flash attention (causal, k-tile 128, 3-stage ring, pipelined) ----------------
#define ASWZ(row, g) ((row) * 256 + (((g) ^ ((row) & 7)) << 4))

__global__ __launch_bounds__(256) void attn_hmma(
    const __half* __restrict__ Qh, const __half* __restrict__ Kh,
    const __half* __restrict__ Vh, __half* __restrict__ AOh)
{
    extern __shared__ char sm[];
    const uint32_t sb = smem_u32(sm);
    constexpr int MTILE = 128 * 128 * 2;    // 32 KB per matrix
    constexpr int STAGE = 2 * MTILE;        // K + V = 64 KB; 3 stages

    const int tid = threadIdx.x, wid = tid >> 5, lane = tid & 31;
    const int h  = blockIdx.y, kh = h >> 2;
    const int bq = gridDim.x - 1 - blockIdx.x;
    const int q0 = bq * 128;
    const int wr = wid * 16;
    const int r  = lane >> 2, c2 = (lane & 3) * 2;
    const int rl = lane & 15, chh = lane >> 4;

    uint32_t qf[8][4];
    {
        const int row0 = q0 + wr + r;
#pragma unroll
        for (int ks = 0; ks < 8; ++ks) {
            int k2 = ks * 16 + c2;
            size_t b00 = (size_t)row0 * QDIM + h * HD + k2;
            size_t b10 = b00 + (size_t)8 * QDIM;
            qf[ks][0] = *(const uint32_t*)(Qh + b00);
            qf[ks][1] = *(const uint32_t*)(Qh + b10);
            qf[ks][2] = *(const uint32_t*)(Qh + b00 + 8);
            qf[ks][3] = *(const uint32_t*)(Qh + b10 + 8);
        }
    }

    float o[16][4];
#pragma unroll
    for (int i = 0; i < 16; ++i)
#pragma unroll
        for (int q = 0; q < 4; ++q) o[i][q] = 0.f;
    float m1 = -1e30f, m2 = -1e30f, l1 = 0.f, l2 = 0.f;

    const int ntiles = bq + 1;

    auto load_kv = [&](int kt, int s) {
        const int k0 = kt * 128;
        const uint32_t st = sb + s * STAGE;
#pragma unroll
        for (int i = 0; i < 8; ++i) {
            int id = tid + i * 256;
            int rw = id >> 4, g = id & 15;
            uint32_t off = ASWZ(rw, g);
            size_t src = (size_t)(k0 + rw) * KVDIM + kh * HD + g * 8;
            cpa16(st + off,         Kh + src);
            cpa16(st + MTILE + off, Vh + src);
        }
        CP_COMMIT();
    };

    load_kv(0, 0);

    int sidx = 0, nsidx = 1;
    for (int kt = 0; kt < ntiles; ++kt) {
        if (kt + 1 < ntiles) {
            load_kv(kt + 1, nsidx);
            nsidx = (nsidx == 2) ? 0 : nsidx + 1;
            CP_WAIT1();
        } else {
            CP_WAIT0();
        }
        __syncthreads();

        const uint32_t st = sb + sidx * STAGE;
        sidx = (sidx == 2) ? 0 : sidx + 1;
        const int k0 = kt * 128;

        float sacc[16][4];
#pragma unroll
        for (int i = 0; i < 16; ++i)
#pragma unroll
            for (int q = 0; q < 4; ++q) sacc[i][q] = 0.f;

        // ---- S = Q @ K^T, pipelined over flattened (ks, np)
        {
            uint32_t kb[2][4];
            ldsm_x4(kb[0][0], kb[0][1], kb[0][2], kb[0][3], st + ASWZ(rl, chh));
#pragma unroll
            for (int it = 0; it < 64; ++it) {
                const int ks = it >> 3, np = it & 7;
                const int cur = it & 1, nxt = cur ^ 1;
                if (it < 63) {
                    const int it2 = it + 1;
                    const int ks2 = it2 >> 3, np2 = it2 & 7;
                    ldsm_x4(kb[nxt][0], kb[nxt][1], kb[nxt][2], kb[nxt][3],
                            st + ASWZ(np2 * 16 + rl, 2 * ks2 + chh));
                }
                float* d0 = sacc[np * 2];
                float* d1 = sacc[np * 2 + 1];
                mma_f16(d0[0], d0[1], d0[2], d0[3],
                        qf[ks][0], qf[ks][1], qf[ks][2], qf[ks][3], kb[cur][0], kb[cur][2]);
                mma_f16(d1[0], d1[1], d1[2], d1[3],
                        qf[ks][0], qf[ks][1], qf[ks][2], qf[ks][3], kb[cur][1], kb[cur][3]);
            }
        }

        if (k0 + 127 > q0 + wr) {
            const int row1 = q0 + wr + r, row2 = row1 + 8;
#pragma unroll
            for (int nt = 0; nt < 16; ++nt) {
                int col = k0 + nt * 8 + c2;
                if (col     > row1) sacc[nt][0] = -1e30f;
                if (col + 1 > row1) sacc[nt][1] = -1e30f;
                if (col     > row2) sacc[nt][2] = -1e30f;
                if (col + 1 > row2) sacc[nt][3] = -1e30f;
            }
        }

        float mx1 = -1e30f, mx2 = -1e30f;
#pragma unroll
        for (int nt = 0; nt < 16; ++nt) {
            mx1 = fmaxf(mx1, fmaxf(sacc[nt][0], sacc[nt][1]));
            mx2 = fmaxf(mx2, fmaxf(sacc[nt][2], sacc[nt][3]));
        }
        mx1 = fmaxf(mx1, __shfl_xor_sync(0xffffffffu, mx1, 1));
        mx1 = fmaxf(mx1, __shfl_xor_sync(0xffffffffu, mx1, 2));
        mx2 = fmaxf(mx2, __shfl_xor_sync(0xffffffffu, mx2, 1));
        mx2 = fmaxf(mx2, __shfl_xor_sync(0xffffffffu, mx2, 2));
        float nm1 = fmaxf(m1, mx1), nm2 = fmaxf(m2, mx2);
        float cf1 = __expf(m1 - nm1), cf2 = __expf(m2 - nm2);
        m1 = nm1; m2 = nm2;

        float ls1 = 0.f, ls2 = 0.f;
#pragma unroll
        for (int nt = 0; nt < 16; ++nt) {
            sacc[nt][0] = __expf(sacc[nt][0] - nm1);
            sacc[nt][1] = __expf(sacc[nt][1] - nm1);
            sacc[nt][2] = __expf(sacc[nt][2] - nm2);
            sacc[nt][3] = __expf(sacc[nt][3] - nm2);
            ls1 += sacc[nt][0] + sacc[nt][1];
            ls2 += sacc[nt][2] + sacc[nt][3];
        }
        ls1 += __shfl_xor_sync(0xffffffffu, ls1, 1);
        ls1 += __shfl_xor_sync(0xffffffffu, ls1, 2);
        ls2 += __shfl_xor_sync(0xffffffffu, ls2, 1);
        ls2 += __shfl_xor_sync(0xffffffffu, ls2, 2);
        l1 = l1 * cf1 + ls1;
        l2 = l2 * cf2 + ls2;
#pragma unroll
        for (int dt = 0; dt < 16; ++dt) {
            o[dt][0] *= cf1; o[dt][1] *= cf1;
            o[dt][2] *= cf2; o[dt][3] *= cf2;
        }

        // ---- O += P @ V, v-frag pipelined within each s
#pragma unroll
        for (int s = 0; s < 8; ++s) {
            uint32_t ap[4];
#pragma unroll
            for (int half = 0; half < 2; ++half) {
                const float* sv = sacc[2 * s + half];
                ap[2 * half + 0] = pack2h(sv[0], sv[1]);
                ap[2 * half + 1] = pack2h(sv[2], sv[3]);
            }
            uint32_t vb[2][4];
            ldsm_x4_t(vb[0][0], vb[0][1], vb[0][2], vb[0][3],
                      st + MTILE + ASWZ(s * 16 + rl, chh));
#pragma unroll
            for (int dg = 0; dg < 8; ++dg) {
                const int cur = dg & 1, nxt = cur ^ 1;
                if (dg < 7) {
                    ldsm_x4_t(vb[nxt][0], vb[nxt][1], vb[nxt][2], vb[nxt][3],
                              st + MTILE + ASWZ(s * 16 + rl, 2 * (dg + 1) + chh));
                }
                float* d0 = o[2 * dg];
                float* d1 = o[2 * dg + 1];
                mma_f16(d0[0], d0[1], d0[2], d0[3], ap[0], ap[1], ap[2], ap[3],
                        vb[cur][0], vb[cur][1]);
                mma_f16(d1[0], d1[1], d1[2], d1[3], ap[0], ap[1], ap[2], ap[3],
                        vb[cur][2], vb[cur][3]);
            }
        }
        // no bottom sync: 3-stage ring, overwrite distance covered by top barriers
    }

    const float inv1 = 1.f / l1, inv2 = 1.f / l2;
    const int row1 = q0 + wr + r;
#pragma unroll
    for (int dt = 0; dt < 16; ++dt) {
        size_t c0 = (size_t)row1 * QDIM + h * HD + dt * 8 + c2;
        size_t c1 = c0 + (size_t)8 * QDIM;
        *(uint32_t*)(AOh + c0) = pack2h(o[dt][0] * inv1, o[dt][1] * inv1);
        *(uint32_t*)(AOh + c1) = pack2h(o[dt][2] * inv2, o[dt][3] * inv2);
    }
}

// ---------------- launch ----------------
extern "C" void kernel_launch(void* const* d_in, const int* in_sizes, int n_in,
                              void* d_out, int out_size)
{
    const float* hs   = (const float*)d_in[0];
    const int*   pos  = (const int*)d_in[2];
    const float* Wq   = (const float*)d_in[3];
    const float* Wk   = (const float*)d_in[4];
    const float* Wv   = (const float*)d_in[5];
    const float* Wo   = (const float*)d_in[6];
    float* out = (float*)d_out;

    __half *ah, *aoh, *qhp, *khp, *vhp, *wqkv, *wo16;
    float *csp, *snp;
    cudaGetSymbolAddress((void**)&ah,   g_Ah);
    cudaGetSymbolAddress((void**)&aoh,  g_AOh);
    cudaGetSymbolAddress((void**)&qhp,  g_Qh);
    cudaGetSymbolAddress((void**)&khp,  g_Kh);
    cudaGetSymbolAddress((void**)&vhp,  g_Vh);
    cudaGetSymbolAddress((void**)&wqkv, g_Wqkv);
    cudaGetSymbolAddress((void**)&wo16, g_Wo16);
    cudaGetSymbolAddress((void**)&csp,  g_cs);
    cudaGetSymbolAddress((void**)&snp,  g_sn);

    const int gemm_smem = 4 * (128 * 64 * 2 + 64 * 256 * 2);  // 196608
    cudaFuncSetAttribute(gemm_hmma<0>, cudaFuncAttributeMaxDynamicSharedMemorySize, gemm_smem);
    cudaFuncSetAttribute(gemm_hmma<1>, cudaFuncAttributeMaxDynamicSharedMemorySize, gemm_smem);
    const int attn_smem = 3 * 2 * 128 * 128 * 2;   // 196608
    cudaFuncSetAttribute(attn_hmma, cudaFuncAttributeMaxDynamicSharedMemorySize, attn_smem);

    // all converts + rope table in one launch
    conv_fused<<<25088, 256>>>(hs, Wq, Wk, Wv, Wo, pos, ah, wqkv, wo16, csp, snp);

    // fused QKV projection + RoPE + fp16 epilogue (N=6144)
    gemm_hmma<1><<<dim3(QKVD / 256, SQ / 128), 256, gemm_smem>>>(
        ah, wqkv, nullptr, qhp, khp, vhp, csp, snp, SQ, QKVD, HID);

    // attention (plain fp16 operands, fp32 softmax/accum, k-tile 128)
    attn_hmma<<<dim3(SQ / 128, NH), 256, attn_smem>>>(qhp, khp, vhp, aoh);

    // output projection (plain fp32 epilogue)
    gemm_hmma<0><<<dim3(HID / 256, SQ / 128), 256, gemm_smem>>>(
        aoh, wo16, out, nullptr, nullptr, nullptr, nullptr, nullptr, SQ, HID, QDIM);
}

// round 14
// speedup vs baseline: 1.0791x; 1.0791x over previous
#include <cuda_runtime.h>
#include <cuda_fp16.h>
#include <math.h>
#include <cstdint>

#define SQ    2048
#define HID   4096
#define NH    32
#define NKV   8
#define HD    128
#define QDIM  (NH*HD)    // 4096
#define KVDIM (NKV*HD)   // 1024
#define QKVD  (QDIM + 2*KVDIM)   // 6144

// ---------------- scratch (static device allocations) ----------------
__device__ __half g_Ah [SQ * HID];
__device__ __half g_AOh[SQ * QDIM];

__device__ __half g_Qh[SQ * QDIM];
__device__ __half g_Kh[SQ * KVDIM];
__device__ __half g_Vh[SQ * KVDIM];

__device__ __half g_Wqkv[HID * QKVD];   // [K=4096, N=6144] natural layout, fp16
__device__ __half g_Wo16[HID * QDIM];   // [K=4096, N=4096] natural layout, fp16

__device__ float g_cs[SQ * 64];         // rope cos table
__device__ float g_sn[SQ * 64];         // rope sin table

// ---------------- PTX helpers (sm_80-era instructions only) ----------------
__device__ __forceinline__ uint32_t smem_u32(const void* p) {
    uint32_t a;
    asm("{ .reg .u64 t; cvta.to.shared.u64 t, %1; cvt.u32.u64 %0, t; }" : "=r"(a) : "l"(p));
    return a;
}

__device__ __forceinline__ void cpa16(uint32_t dst, const void* src) {
    asm volatile("cp.async.cg.shared.global [%0], [%1], 16;" :: "r"(dst), "l"(src) : "memory");
}
#define CP_COMMIT() asm volatile("cp.async.commit_group;" ::: "memory")
#define CP_WAIT1()  asm volatile("cp.async.wait_group 1;" ::: "memory")
#define CP_WAIT0()  asm volatile("cp.async.wait_group 0;" ::: "memory")

__device__ __forceinline__ void ldsm_x4(uint32_t& r0, uint32_t& r1, uint32_t& r2, uint32_t& r3,
                                        uint32_t addr) {
    asm volatile("ldmatrix.sync.aligned.m8n8.x4.shared.b16 {%0,%1,%2,%3}, [%4];"
                 : "=r"(r0), "=r"(r1), "=r"(r2), "=r"(r3) : "r"(addr));
}
__device__ __forceinline__ void ldsm_x4_t(uint32_t& r0, uint32_t& r1, uint32_t& r2, uint32_t& r3,
                                          uint32_t addr) {
    asm volatile("ldmatrix.sync.aligned.m8n8.x4.trans.shared.b16 {%0,%1,%2,%3}, [%4];"
                 : "=r"(r0), "=r"(r1), "=r"(r2), "=r"(r3) : "r"(addr));
}

__device__ __forceinline__ void mma_f16(float& d0, float& d1, float& d2, float& d3,
                                        uint32_t a0, uint32_t a1, uint32_t a2, uint32_t a3,
                                        uint32_t b0, uint32_t b1) {
    asm volatile("mma.sync.aligned.m16n8k16.row.col.f32.f16.f16.f32 "
                 "{%0,%1,%2,%3}, {%4,%5,%6,%7}, {%8,%9}, {%0,%1,%2,%3};"
                 : "+f"(d0), "+f"(d1), "+f"(d2), "+f"(d3)
                 : "r"(a0), "r"(a1), "r"(a2), "r"(a3), "r"(b0), "r"(b1));
}

__device__ __forceinline__ uint32_t pack2h(float a, float b) {
    __half2 h;
    h.x = __float2half_rn(a);
    h.y = __float2half_rn(b);
    return *(uint32_t*)&h;
}

// ---------------- fused prep: hs convert + 4 weight converts + rope table ----------------
__global__ __launch_bounds__(256) void conv_fused(
    const float* __restrict__ hs,
    const float* __restrict__ Wq, const float* __restrict__ Wk,
    const float* __restrict__ Wv, const float* __restrict__ Wo,
    const int* __restrict__ pos_ids,
    __half* __restrict__ ah, __half* __restrict__ wqkv, __half* __restrict__ wo16,
    float* __restrict__ cs_tab, float* __restrict__ sn_tab)
{
    int b = blockIdx.x;
    if (b >= 24576) {
        int idx = (b - 24576) * 256 + threadIdx.x;
        int s = idx >> 6, i = idx & 63;
        double invf = exp(-(double)i * (9.210340371976184 / 64.0));
        float ang = (float)((double)pos_ids[s] * invf);
        float c, si;
        sincosf(ang, &si, &c);
        cs_tab[idx] = c;
        sn_tab[idx] = si;
        return;
    }
    if (b < 4096) {
        int i = b * 256 + threadIdx.x;
        float4 a = ((const float4*)hs)[2 * i];
        float4 c = ((const float4*)hs)[2 * i + 1];
        uint4 o;
        o.x = pack2h(a.x, a.y);
        o.y = pack2h(a.z, a.w);
        o.z = pack2h(c.x, c.y);
        o.w = pack2h(c.z, c.w);
        ((uint4*)ah)[i] = o;
        return;
    }
    b -= 4096;
    const float* W; __half* D; int nq, coff, stride;
    if (b < 8192)        { W = Wq; D = wqkv; nq = 4096 / 8; coff = 0;    stride = QKVD; }
    else if (b < 10240)  { b -= 8192;  W = Wk; D = wqkv; nq = 1024 / 8; coff = 4096; stride = QKVD; }
    else if (b < 12288)  { b -= 10240; W = Wv; D = wqkv; nq = 1024 / 8; coff = 5120; stride = QKVD; }
    else                 { b -= 12288; W = Wo; D = wo16; nq = 4096 / 8; coff = 0;    stride = 4096; }

    int idx = b * 256 + threadIdx.x;
    int k = idx / nq, nc = (idx - k * nq) << 3;
    const float* src = W + (size_t)k * (nq << 3) + nc;
    float4 a = *(const float4*)src;
    float4 c = *(const float4*)(src + 4);
    uint4 o;
    o.x = pack2h(a.x, a.y);
    o.y = pack2h(a.z, a.w);
    o.z = pack2h(c.x, c.y);
    o.w = pack2h(c.z, c.w);
    *(uint4*)(D + (size_t)k * stride + coff + nc) = o;
}

// ---------------- HMMA fp16 GEMM, CTA 128x128, warp 64x32, 2 CTAs/SM ----------------
// C[M,N] fp32 = A[M,K] @ B[K,N]. 8 warps 2(m) x 4(n), k-chunk 64, 3-stage cp.async,
// trans-ldsm for B (256B rows).
// EPI==0: plain fp32 C store. EPI==1: fused RoPE/convert epilogue -> Qh/Kh/Vh fp16.
#define SWZ64(r, c8) ((r) * 128 + (((c8) ^ ((r) & 7)) << 4))
#define BSWZ(r, g)   ((r) * 256 + (((g) ^ ((r) & 7)) << 4))

template <int EPI>
__global__ __launch_bounds__(256, 2) void gemm_hmma(
    const __half* __restrict__ A, const __half* __restrict__ B,
    float* __restrict__ C,
    __half* __restrict__ Qh, __half* __restrict__ Kh, __half* __restrict__ Vh,
    const float* __restrict__ cs_tab, const float* __restrict__ sn_tab,
    int M, int N, int K)
{
    extern __shared__ char smem[];
    constexpr int TILE_A = 128 * 64 * 2;    // 16 KB
    constexpr int TILE_B = 64 * 128 * 2;    // 16 KB (64 k-rows x 256B)
    constexpr int STAGE  = TILE_A + TILE_B; // 32 KB; 3 stages = 96 KB
    const uint32_t sb = smem_u32(smem);

    const int tid  = threadIdx.x;
    const int wid  = tid >> 5;
    const int lane = tid & 31;
    const int m0 = blockIdx.y * 128;
    const int n0 = blockIdx.x * 128;
    const int wm = (wid >> 2) * 64;      // 0 or 64
    const int wn = (wid & 3) * 32;       // 0..96
    const int nk = K >> 6;

    const int rl  = lane & 15;
    const int ch  = lane >> 4;

    float acc[4][4][4];
#pragma unroll
    for (int i = 0; i < 4; ++i)
#pragma unroll
        for (int j = 0; j < 4; ++j)
#pragma unroll
            for (int q = 0; q < 4; ++q) acc[i][j][q] = 0.f;

    auto load_stage = [&](int c, int s) {
        const int kb = c * 64;
        const uint32_t st = sb + s * STAGE;
#pragma unroll
        for (int i = 0; i < 4; ++i) {     // A: 128 rows x 128B
            int id = tid + i * 256;
            int r = id >> 3, c8 = id & 7;
            cpa16(st + SWZ64(r, c8), A + (size_t)(m0 + r) * K + kb + c8 * 8);
        }
#pragma unroll
        for (int i = 0; i < 4; ++i) {     // B: 64 k-rows x 256B
            int id = tid + i * 256;
            int r = id >> 4, g = id & 15;
            cpa16(st + TILE_A + BSWZ(r, g), B + (size_t)(kb + r) * N + n0 + g * 8);
        }
        CP_COMMIT();
    };

    load_stage(0, 0);
    if (nk > 1) load_stage(1, 1);

    int sidx = 0, nsidx = 2;
    for (int c = 0; c < nk; ++c) {
        if (c + 1 < nk) { CP_WAIT1(); } else { CP_WAIT0(); }
        __syncthreads();
        if (c + 2 < nk) {
            load_stage(c + 2, nsidx);
            nsidx = (nsidx == 2) ? 0 : nsidx + 1;
        }

        const uint32_t st = sb + sidx * STAGE;
        sidx = (sidx == 2) ? 0 : sidx + 1;
        const uint32_t stb = st + TILE_A;
        const int gb0 = wn >> 3;          // 16B-group base for this warp's 32 cols
#pragma unroll
        for (int ks = 0; ks < 4; ++ks) {
            uint32_t af[4][4], bf[2][4];
#pragma unroll
            for (int mt = 0; mt < 4; ++mt)
                ldsm_x4(af[mt][0], af[mt][1], af[mt][2], af[mt][3],
                        st + SWZ64(wm + mt * 16 + rl, 2 * ks + ch));
#pragma unroll
            for (int np = 0; np < 2; ++np)
                ldsm_x4_t(bf[np][0], bf[np][1], bf[np][2], bf[np][3],
                          stb + BSWZ(ks * 16 + rl, gb0 + np * 2 + ch));
#pragma unroll
            for (int np = 0; np < 2; ++np) {
#pragma unroll
                for (int mt = 0; mt < 4; ++mt) {
                    float* d0 = acc[mt][np * 2];
                    float* d1 = acc[mt][np * 2 + 1];
                    mma_f16(d0[0], d0[1], d0[2], d0[3],
                            af[mt][0], af[mt][1], af[mt][2], af[mt][3],
                            bf[np][0], bf[np][1]);
                    mma_f16(d1[0], d1[1], d1[2], d1[3],
                            af[mt][0], af[mt][1], af[mt][2], af[mt][3],
                            bf[np][2], bf[np][3]);
                }
            }
        }
    }

    if (EPI == 0) {
#pragma unroll
        for (int mt = 0; mt < 4; ++mt) {
#pragma unroll
            for (int nt = 0; nt < 4; ++nt) {
                int rg = m0 + wm + mt * 16 + (lane >> 2);
                int cg = n0 + wn + nt * 8 + (lane & 3) * 2;
                float* d = acc[mt][nt];
                *(float2*)(C + (size_t)rg * N + cg)       = make_float2(d[0], d[1]);
                *(float2*)(C + (size_t)(rg + 8) * N + cg) = make_float2(d[2], d[3]);
            }
        }
    } else {
        // fused QKV epilogue: stage acc tile (128x128 fp32) to smem, RoPE/convert -> fp16.
        __syncthreads();
        float* sf = (float*)smem;
        constexpr int RS = 132;
#pragma unroll
        for (int mt = 0; mt < 4; ++mt) {
#pragma unroll
            for (int nt = 0; nt < 4; ++nt) {
                int rl_ = wm + mt * 16 + (lane >> 2);
                int cl_ = wn + nt * 8 + (lane & 3) * 2;
                float* d = acc[mt][nt];
                *(float2*)(sf + rl_ * RS + cl_)       = make_float2(d[0], d[1]);
                *(float2*)(sf + (rl_ + 8) * RS + cl_) = make_float2(d[2], d[3]);
            }
        }
        __syncthreads();

        const float qscale = 0.08838834764831845f;
        const int q4 = (tid & 15) << 2;              // quad within head (0..60)
        const int rbase = (tid >> 4) * 8;            // 16 groups x 8 rows
        const bool isQ = (n0 < QDIM);
        const bool isK = (n0 >= QDIM) && (n0 < QDIM + KVDIM);

#pragma unroll
        for (int rr = 0; rr < 8; ++rr) {
            int row = rbase + rr;
            int grow = m0 + row;
            const float* bp = sf + row * RS + q4;
            float4 x0 = *(const float4*)bp;
            float4 x1 = *(const float4*)(bp + 64);
            uint2 lo, hi;
            if (isQ || isK) {
                float4 c4 = *(const float4*)(cs_tab + (size_t)grow * 64 + q4);
                float4 s4 = *(const float4*)(sn_tab + (size_t)grow * 64 + q4);
                if (isQ) {
                    lo.x = pack2h((x0.x * c4.x - x1.x * s4.x) * qscale,
                                  (x0.y * c4.y - x1.y * s4.y) * qscale);
                    lo.y = pack2h((x0.z * c4.z - x1.z * s4.z) * qscale,
                                  (x0.w * c4.w - x1.w * s4.w) * qscale);
                    hi.x = pack2h((x1.x * c4.x + x0.x * s4.x) * qscale,
                                  (x1.y * c4.y + x0.y * s4.y) * qscale);
                    hi.y = pack2h((x1.z * c4.z + x0.z * s4.z) * qscale,
                                  (x1.w * c4.w + x0.w * s4.w) * qscale);
                } else {
                    lo.x = pack2h(x0.x * c4.x - x1.x * s4.x, x0.y * c4.y - x1.y * s4.y);
                    lo.y = pack2h(x0.z * c4.z - x1.z * s4.z, x0.w * c4.w - x1.w * s4.w);
                    hi.x = pack2h(x1.x * c4.x + x0.x * s4.x, x1.y * c4.y + x0.y * s4.y);
                    hi.y = pack2h(x1.z * c4.z + x0.z * s4.z, x1.w * c4.w + x0.w * s4.w);
                }
            } else {
                lo.x = pack2h(x0.x, x0.y); lo.y = pack2h(x0.z, x0.w);
                hi.x = pack2h(x1.x, x1.y); hi.y = pack2h(x1.z, x1.w);
            }
            __half* dst;
            if (isQ)      dst = Qh + (size_t)grow * QDIM + n0 + q4;
            else if (isK) dst = Kh + (size_t)grow * KVDIM + (n0 - QDIM) + q4;
            else          dst = Vh + (size_t)grow * KVDIM + (n0 - QDIM - KVDIM) + q4;
            *(uint2*)dst        = lo;
            *(uint2*)(dst + 64) = hi;
        }
    }
}

// ---------------- HMMA flash attention (causal, k-tile 128, 3-stage ring) ----------------
#define ASWZ(row, g) ((row) * 256 + (((g) ^ ((row) & 7)) << 4))

__global__ __launch_bounds__(256) void attn_hmma(
    const __half* __restrict__ Qh, const __half* __restrict__ Kh,
    const __half* __restrict__ Vh, __half* __restrict__ AOh)
{
    extern __shared__ char sm[];
    const uint32_t sb = smem_u32(sm);
    constexpr int MTILE = 128 * 128 * 2;    // 32 KB per matrix
    constexpr int STAGE = 2 * MTILE;        // K + V = 64 KB; 3 stages

    const int tid = threadIdx.x, wid = tid >> 5, lane = tid & 31;
    const int h  = blockIdx.y, kh = h >> 2;
    const int bq = gridDim.x - 1 - blockIdx.x;
    const int q0 = bq * 128;
    const int wr = wid * 16;
    const int r  = lane >> 2, c2 = (lane & 3) * 2;
    const int rl = lane & 15, chh = lane >> 4;

    uint32_t qf[8][4];
    {
        const int row0 = q0 + wr + r;
#pragma unroll
        for (int ks = 0; ks < 8; ++ks) {
            int k2 = ks * 16 + c2;
            size_t b00 = (size_t)row0 * QDIM + h * HD + k2;
            size_t b10 = b00 + (size_t)8 * QDIM;
            qf[ks][0] = *(const uint32_t*)(Qh + b00);
            qf[ks][1] = *(const uint32_t*)(Qh + b10);
            qf[ks][2] = *(const uint32_t*)(Qh + b00 + 8);
            qf[ks][3] = *(const uint32_t*)(Qh + b10 + 8);
        }
    }

    float o[16][4];
#pragma unroll
    for (int i = 0; i < 16; ++i)
#pragma unroll
        for (int q = 0; q < 4; ++q) o[i][q] = 0.f;
    float m1 = -1e30f, m2 = -1e30f, l1 = 0.f, l2 = 0.f;

    const int ntiles = bq + 1;

    auto load_kv = [&](int kt, int s) {
        const int k0 = kt * 128;
        const uint32_t st = sb + s * STAGE;
#pragma unroll
        for (int i = 0; i < 8; ++i) {
            int id = tid + i * 256;
            int rw = id >> 4, g = id & 15;
            uint32_t off = ASWZ(rw, g);
            size_t src = (size_t)(k0 + rw) * KVDIM + kh * HD + g * 8;
            cpa16(st + off,         Kh + src);
            cpa16(st + MTILE + off, Vh + src);
        }
        CP_COMMIT();
    };

    load_kv(0, 0);

    int sidx = 0, nsidx = 1;
    for (int kt = 0; kt < ntiles; ++kt) {
        if (kt + 1 < ntiles) {
            load_kv(kt + 1, nsidx);
            nsidx = (nsidx == 2) ? 0 : nsidx + 1;
            CP_WAIT1();
        } else {
            CP_WAIT0();
        }
        __syncthreads();

        const uint32_t st = sb + sidx * STAGE;
        sidx = (sidx == 2) ? 0 : sidx + 1;
        const int k0 = kt * 128;

        float sacc[16][4];
#pragma unroll
        for (int i = 0; i < 16; ++i)
#pragma unroll
            for (int q = 0; q < 4; ++q) sacc[i][q] = 0.f;

#pragma unroll
        for (int ks = 0; ks < 8; ++ks) {
#pragma unroll
            for (int np = 0; np < 8; ++np) {
                uint32_t b0, b1, b2, b3;
                ldsm_x4(b0, b1, b2, b3, st + ASWZ(np * 16 + rl, 2 * ks + chh));
                float* d0 = sacc[np * 2];
                float* d1 = sacc[np * 2 + 1];
                mma_f16(d0[0], d0[1], d0[2], d0[3],
                        qf[ks][0], qf[ks][1], qf[ks][2], qf[ks][3], b0, b2);
                mma_f16(d1[0], d1[1], d1[2], d1[3],
                        qf[ks][0], qf[ks][1], qf[ks][2], qf[ks][3], b1, b3);
            }
        }

        if (k0 + 127 > q0 + wr) {
            const int row1 = q0 + wr + r, row2 = row1 + 8;
#pragma unroll
            for (int nt = 0; nt < 16; ++nt) {
                int col = k0 + nt * 8 + c2;
                if (col     > row1) sacc[nt][0] = -1e30f;
                if (col + 1 > row1) sacc[nt][1] = -1e30f;
                if (col     > row2) sacc[nt][2] = -1e30f;
                if (col + 1 > row2) sacc[nt][3] = -1e30f;
            }
        }

        float mx1 = -1e30f, mx2 = -1e30f;
#pragma unroll
        for (int nt = 0; nt < 16; ++nt) {
            mx1 = fmaxf(mx1, fmaxf(sacc[nt][0], sacc[nt][1]));
            mx2 = fmaxf(mx2, fmaxf(sacc[nt][2], sacc[nt][3]));
        }
        mx1 = fmaxf(mx1, __shfl_xor_sync(0xffffffffu, mx1, 1));
        mx1 = fmaxf(mx1, __shfl_xor_sync(0xffffffffu, mx1, 2));
        mx2 = fmaxf(mx2, __shfl_xor_sync(0xffffffffu, mx2, 1));
        mx2 = fmaxf(mx2, __shfl_xor_sync(0xffffffffu, mx2, 2));
        float nm1 = fmaxf(m1, mx1), nm2 = fmaxf(m2, mx2);
        float cf1 = __expf(m1 - nm1), cf2 = __expf(m2 - nm2);
        m1 = nm1; m2 = nm2;

        float ls1 = 0.f, ls2 = 0.f;
#pragma unroll
        for (int nt = 0; nt < 16; ++nt) {
            sacc[nt][0] = __expf(sacc[nt][0] - nm1);
            sacc[nt][1] = __expf(sacc[nt][1] - nm1);
            sacc[nt][2] = __expf(sacc[nt][2] - nm2);
            sacc[nt][3] = __expf(sacc[nt][3] - nm2);
            ls1 += sacc[nt][0] + sacc[nt][1];
            ls2 += sacc[nt][2] + sacc[nt][3];
        }
        ls1 += __shfl_xor_sync(0xffffffffu, ls1, 1);
        ls1 += __shfl_xor_sync(0xffffffffu, ls1, 2);
        ls2 += __shfl_xor_sync(0xffffffffu, ls2, 1);
        ls2 += __shfl_xor_sync(0xffffffffu, ls2, 2);
        l1 = l1 * cf1 + ls1;
        l2 = l2 * cf2 + ls2;
#pragma unroll
        for (int dt = 0; dt < 16; ++dt) {
            o[dt][0] *= cf1; o[dt][1] *= cf1;
            o[dt][2] *= cf2; o[dt][3] *= cf2;
        }

#pragma unroll
        for (int s = 0; s < 8; ++s) {
            uint32_t ap[4];
#pragma unroll
            for (int half = 0; half < 2; ++half) {
                const float* sv = sacc[2 * s + half];
                ap[2 * half + 0] = pack2h(sv[0], sv[1]);
                ap[2 * half + 1] = pack2h(sv[2], sv[3]);
            }
#pragma unroll
            for (int dg = 0; dg < 8; ++dg) {
                uint32_t v0, v1, v2, v3;
                ldsm_x4_t(v0, v1, v2, v3,
                          st + MTILE + ASWZ(s * 16 + rl, 2 * dg + chh));
                float* d0 = o[2 * dg];
                float* d1 = o[2 * dg + 1];
                mma_f16(d0[0], d0[1], d0[2], d0[3], ap[0], ap[1], ap[2], ap[3], v0, v1);
                mma_f16(d1[0], d1[1], d1[2], d1[3], ap[0], ap[1], ap[2], ap[3], v2, v3);
            }
        }
    }

    const float inv1 = 1.f / l1, inv2 = 1.f / l2;
    const int row1 = q0 + wr + r;
#pragma unroll
    for (int dt = 0; dt < 16; ++dt) {
        size_t c0 = (size_t)row1 * QDIM + h * HD + dt * 8 + c2;
        size_t c1 = c0 + (size_t)8 * QDIM;
        *(uint32_t*)(AOh + c0) = pack2h(o[dt][0] * inv1, o[dt][1] * inv1);
        *(uint32_t*)(AOh + c1) = pack2h(o[dt][2] * inv2, o[dt][3] * inv2);
    }
}

// ---------------- launch ----------------
extern "C" void kernel_launch(void* const* d_in, const int* in_sizes, int n_in,
                              void* d_out, int out_size)
{
    const float* hs   = (const float*)d_in[0];
    const int*   pos  = (const int*)d_in[2];
    const float* Wq   = (const float*)d_in[3];
    const float* Wk   = (const float*)d_in[4];
    const float* Wv   = (const float*)d_in[5];
    const float* Wo   = (const float*)d_in[6];
    float* out = (float*)d_out;

    __half *ah, *aoh, *qhp, *khp, *vhp, *wqkv, *wo16;
    float *csp, *snp;
    cudaGetSymbolAddress((void**)&ah,   g_Ah);
    cudaGetSymbolAddress((void**)&aoh,  g_AOh);
    cudaGetSymbolAddress((void**)&qhp,  g_Qh);
    cudaGetSymbolAddress((void**)&khp,  g_Kh);
    cudaGetSymbolAddress((void**)&vhp,  g_Vh);
    cudaGetSymbolAddress((void**)&wqkv, g_Wqkv);
    cudaGetSymbolAddress((void**)&wo16, g_Wo16);
    cudaGetSymbolAddress((void**)&csp,  g_cs);
    cudaGetSymbolAddress((void**)&snp,  g_sn);

    const int gemm_smem = 3 * (128 * 64 * 2 + 64 * 128 * 2);  // 98304
    cudaFuncSetAttribute(gemm_hmma<0>, cudaFuncAttributeMaxDynamicSharedMemorySize, gemm_smem);
    cudaFuncSetAttribute(gemm_hmma<1>, cudaFuncAttributeMaxDynamicSharedMemorySize, gemm_smem);
    const int attn_smem = 3 * 2 * 128 * 128 * 2;   // 196608
    cudaFuncSetAttribute(attn_hmma, cudaFuncAttributeMaxDynamicSharedMemorySize, attn_smem);

    // all converts + rope table in one launch
    conv_fused<<<25088, 256>>>(hs, Wq, Wk, Wv, Wo, pos, ah, wqkv, wo16, csp, snp);

    // fused QKV projection + RoPE + fp16 epilogue (N=6144)
    gemm_hmma<1><<<dim3(QKVD / 128, SQ / 128), 256, gemm_smem>>>(
        ah, wqkv, nullptr, qhp, khp, vhp, csp, snp, SQ, QKVD, HID);

    // attention (plain fp16 operands, fp32 softmax/accum, k-tile 128)
    attn_hmma<<<dim3(SQ / 128, NH), 256, attn_smem>>>(qhp, khp, vhp, aoh);

    // output projection (plain fp32 epilogue)
    gemm_hmma<0><<<dim3(HID / 128, SQ / 128), 256, gemm_smem>>>(
        aoh, wo16, out, nullptr, nullptr, nullptr, nullptr, nullptr, SQ, HID, QDIM);
}

// round 16
// speedup vs baseline: 1.0907x; 1.0108x over previous
#include <cuda_runtime.h>
#include <cuda_fp16.h>
#include <math.h>
#include <cstdint>

#define SQ    2048
#define HID   4096
#define NH    32
#define NKV   8
#define HD    128
#define QDIM  (NH*HD)    // 4096
#define KVDIM (NKV*HD)   // 1024
#define QKVD  (QDIM + 2*KVDIM)   // 6144

// ---------------- scratch (static device allocations) ----------------
__device__ __half g_Ah [SQ * HID];
__device__ __half g_AOh[SQ * QDIM];

__device__ __half g_Qh[SQ * QDIM];
__device__ __half g_Kh[SQ * KVDIM];
__device__ __half g_Vh[SQ * KVDIM];

__device__ __half g_Wqkv[HID * QKVD];   // [K=4096, N=6144] natural layout, fp16
__device__ __half g_Wo16[HID * QDIM];   // [K=4096, N=4096] natural layout, fp16

__device__ float g_cs[SQ * 64];         // rope cos table
__device__ float g_sn[SQ * 64];         // rope sin table

// ---------------- PTX helpers (sm_80-era instructions only) ----------------
__device__ __forceinline__ uint32_t smem_u32(const void* p) {
    uint32_t a;
    asm("{ .reg .u64 t; cvta.to.shared.u64 t, %1; cvt.u32.u64 %0, t; }" : "=r"(a) : "l"(p));
    return a;
}

__device__ __forceinline__ void cpa16(uint32_t dst, const void* src) {
    asm volatile("cp.async.cg.shared.global [%0], [%1], 16;" :: "r"(dst), "l"(src) : "memory");
}
#define CP_COMMIT() asm volatile("cp.async.commit_group;" ::: "memory")
#define CP_WAIT1()  asm volatile("cp.async.wait_group 1;" ::: "memory")
#define CP_WAIT0()  asm volatile("cp.async.wait_group 0;" ::: "memory")

__device__ __forceinline__ void ldsm_x4(uint32_t& r0, uint32_t& r1, uint32_t& r2, uint32_t& r3,
                                        uint32_t addr) {
    asm volatile("ldmatrix.sync.aligned.m8n8.x4.shared.b16 {%0,%1,%2,%3}, [%4];"
                 : "=r"(r0), "=r"(r1), "=r"(r2), "=r"(r3) : "r"(addr));
}
__device__ __forceinline__ void ldsm_x4_t(uint32_t& r0, uint32_t& r1, uint32_t& r2, uint32_t& r3,
                                          uint32_t addr) {
    asm volatile("ldmatrix.sync.aligned.m8n8.x4.trans.shared.b16 {%0,%1,%2,%3}, [%4];"
                 : "=r"(r0), "=r"(r1), "=r"(r2), "=r"(r3) : "r"(addr));
}

__device__ __forceinline__ void mma_f16(float& d0, float& d1, float& d2, float& d3,
                                        uint32_t a0, uint32_t a1, uint32_t a2, uint32_t a3,
                                        uint32_t b0, uint32_t b1) {
    asm volatile("mma.sync.aligned.m16n8k16.row.col.f32.f16.f16.f32 "
                 "{%0,%1,%2,%3}, {%4,%5,%6,%7}, {%8,%9}, {%0,%1,%2,%3};"
                 : "+f"(d0), "+f"(d1), "+f"(d2), "+f"(d3)
                 : "r"(a0), "r"(a1), "r"(a2), "r"(a3), "r"(b0), "r"(b1));
}

__device__ __forceinline__ uint32_t pack2h(float a, float b) {
    __half2 h;
    h.x = __float2half_rn(a);
    h.y = __float2half_rn(b);
    return *(uint32_t*)&h;
}

// ---------------- fused prep (4 items/thread for MLP) ----------------
// item-blocks: hs 4096 | Wq 8192, Wk 2048, Wv 2048, Wo 8192 (=20480 weight)
// blocks: [0,1024) hs | [1024,6144) weights | [6144,6272) rope table
__global__ __launch_bounds__(256) void conv_fused(
    const float* __restrict__ hs,
    const float* __restrict__ Wq, const float* __restrict__ Wk,
    const float* __restrict__ Wv, const float* __restrict__ Wo,
    const int* __restrict__ pos_ids,
    __half* __restrict__ ah, __half* __restrict__ wqkv, __half* __restrict__ wo16,
    float* __restrict__ cs_tab, float* __restrict__ sn_tab)
{
    const int b = blockIdx.x;
    const int tid = threadIdx.x;
    if (b >= 6144) {
        // rope table: 4 entries per thread (131072 entries total)
#pragma unroll
        for (int j = 0; j < 4; ++j) {
            int idx = (b - 6144) * 1024 + j * 256 + tid;
            int s = idx >> 6, i = idx & 63;
            double invf = exp(-(double)i * (9.210340371976184 / 64.0));
            float ang = (float)((double)pos_ids[s] * invf);
            float c, si;
            sincosf(ang, &si, &c);
            cs_tab[idx] = c;
            sn_tab[idx] = si;
        }
        return;
    }
    if (b < 1024) {
        // hs: 4 x (8 floats) per thread, independent loads batched
        float4 a[4], c[4];
#pragma unroll
        for (int j = 0; j < 4; ++j) {
            int i = b * 1024 + j * 256 + tid;
            a[j] = ((const float4*)hs)[2 * i];
            c[j] = ((const float4*)hs)[2 * i + 1];
        }
#pragma unroll
        for (int j = 0; j < 4; ++j) {
            int i = b * 1024 + j * 256 + tid;
            uint4 o;
            o.x = pack2h(a[j].x, a[j].y);
            o.y = pack2h(a[j].z, a[j].w);
            o.z = pack2h(c[j].x, c[j].y);
            o.w = pack2h(c[j].z, c[j].w);
            ((uint4*)ah)[i] = o;
        }
        return;
    }
    // weights: block covers 4 consecutive item-blocks, all in one region
    // (region boundaries 8192/10240/12288 are multiples of 4)
    const int ib0 = (b - 1024) * 4;       // 0 .. 20476
    const float* W; __half* D; int nq, coff, stride, rb;
    if (ib0 < 8192)       { W = Wq; D = wqkv; nq = 4096 / 8; coff = 0;    stride = QKVD; rb = ib0; }
    else if (ib0 < 10240) { W = Wk; D = wqkv; nq = 1024 / 8; coff = 4096; stride = QKVD; rb = ib0 - 8192; }
    else if (ib0 < 12288) { W = Wv; D = wqkv; nq = 1024 / 8; coff = 5120; stride = QKVD; rb = ib0 - 10240; }
    else                  { W = Wo; D = wo16; nq = 4096 / 8; coff = 0;    stride = 4096; rb = ib0 - 12288; }

    float4 a[4], c[4];
    int ks[4], ncs[4];
#pragma unroll
    for (int j = 0; j < 4; ++j) {
        int idx = (rb + j) * 256 + tid;
        ks[j] = idx / nq;
        ncs[j] = (idx - ks[j] * nq) << 3;
        const float* src = W + (size_t)ks[j] * (nq << 3) + ncs[j];
        a[j] = *(const float4*)src;
        c[j] = *(const float4*)(src + 4);
    }
#pragma unroll
    for (int j = 0; j < 4; ++j) {
        uint4 o;
        o.x = pack2h(a[j].x, a[j].y);
        o.y = pack2h(a[j].z, a[j].w);
        o.z = pack2h(c[j].x, c[j].y);
        o.w = pack2h(c[j].z, c[j].w);
        *(uint4*)(D + (size_t)ks[j] * stride + coff + ncs[j]) = o;
    }
}

// ---------------- HMMA fp16 GEMM, CTA 128x128, warp 64x32, 2 CTAs/SM ----------------
#define SWZ64(r, c8) ((r) * 128 + (((c8) ^ ((r) & 7)) << 4))
#define BSWZ(r, g)   ((r) * 256 + (((g) ^ ((r) & 7)) << 4))

template <int EPI>
__global__ __launch_bounds__(256, 2) void gemm_hmma(
    const __half* __restrict__ A, const __half* __restrict__ B,
    float* __restrict__ C,
    __half* __restrict__ Qh, __half* __restrict__ Kh, __half* __restrict__ Vh,
    const float* __restrict__ cs_tab, const float* __restrict__ sn_tab,
    int M, int N, int K)
{
    extern __shared__ char smem[];
    constexpr int TILE_A = 128 * 64 * 2;    // 16 KB
    constexpr int TILE_B = 64 * 128 * 2;    // 16 KB
    constexpr int STAGE  = TILE_A + TILE_B; // 32 KB; 3 stages
    const uint32_t sb = smem_u32(smem);

    const int tid  = threadIdx.x;
    const int wid  = tid >> 5;
    const int lane = tid & 31;
    const int m0 = blockIdx.y * 128;
    const int n0 = blockIdx.x * 128;
    const int wm = (wid >> 2) * 64;
    const int wn = (wid & 3) * 32;
    const int nk = K >> 6;

    const int rl  = lane & 15;
    const int ch  = lane >> 4;

    float acc[4][4][4];
#pragma unroll
    for (int i = 0; i < 4; ++i)
#pragma unroll
        for (int j = 0; j < 4; ++j)
#pragma unroll
            for (int q = 0; q < 4; ++q) acc[i][j][q] = 0.f;

    auto load_stage = [&](int c, int s) {
        const int kb = c * 64;
        const uint32_t st = sb + s * STAGE;
#pragma unroll
        for (int i = 0; i < 4; ++i) {
            int id = tid + i * 256;
            int r = id >> 3, c8 = id & 7;
            cpa16(st + SWZ64(r, c8), A + (size_t)(m0 + r) * K + kb + c8 * 8);
        }
#pragma unroll
        for (int i = 0; i < 4; ++i) {
            int id = tid + i * 256;
            int r = id >> 4, g = id & 15;
            cpa16(st + TILE_A + BSWZ(r, g), B + (size_t)(kb + r) * N + n0 + g * 8);
        }
        CP_COMMIT();
    };

    load_stage(0, 0);
    if (nk > 1) load_stage(1, 1);

    int sidx = 0, nsidx = 2;
    for (int c = 0; c < nk; ++c) {
        if (c + 1 < nk) { CP_WAIT1(); } else { CP_WAIT0(); }
        __syncthreads();
        if (c + 2 < nk) {
            load_stage(c + 2, nsidx);
            nsidx = (nsidx == 2) ? 0 : nsidx + 1;
        }

        const uint32_t st = sb + sidx * STAGE;
        sidx = (sidx == 2) ? 0 : sidx + 1;
        const uint32_t stb = st + TILE_A;
        const int gb0 = wn >> 3;
#pragma unroll
        for (int ks = 0; ks < 4; ++ks) {
            uint32_t af[4][4], bf[2][4];
#pragma unroll
            for (int mt = 0; mt < 4; ++mt)
                ldsm_x4(af[mt][0], af[mt][1], af[mt][2], af[mt][3],
                        st + SWZ64(wm + mt * 16 + rl, 2 * ks + ch));
#pragma unroll
            for (int np = 0; np < 2; ++np)
                ldsm_x4_t(bf[np][0], bf[np][1], bf[np][2], bf[np][3],
                          stb + BSWZ(ks * 16 + rl, gb0 + np * 2 + ch));
#pragma unroll
            for (int np = 0; np < 2; ++np) {
#pragma unroll
                for (int mt = 0; mt < 4; ++mt) {
                    float* d0 = acc[mt][np * 2];
                    float* d1 = acc[mt][np * 2 + 1];
                    mma_f16(d0[0], d0[1], d0[2], d0[3],
                            af[mt][0], af[mt][1], af[mt][2], af[mt][3],
                            bf[np][0], bf[np][1]);
                    mma_f16(d1[0], d1[1], d1[2], d1[3],
                            af[mt][0], af[mt][1], af[mt][2], af[mt][3],
                            bf[np][2], bf[np][3]);
                }
            }
        }
    }

    if (EPI == 0) {
#pragma unroll
        for (int mt = 0; mt < 4; ++mt) {
#pragma unroll
            for (int nt = 0; nt < 4; ++nt) {
                int rg = m0 + wm + mt * 16 + (lane >> 2);
                int cg = n0 + wn + nt * 8 + (lane & 3) * 2;
                float* d = acc[mt][nt];
                *(float2*)(C + (size_t)rg * N + cg)       = make_float2(d[0], d[1]);
                *(float2*)(C + (size_t)(rg + 8) * N + cg) = make_float2(d[2], d[3]);
            }
        }
    } else {
        __syncthreads();
        float* sf = (float*)smem;
        constexpr int RS = 132;
#pragma unroll
        for (int mt = 0; mt < 4; ++mt) {
#pragma unroll
            for (int nt = 0; nt < 4; ++nt) {
                int rl_ = wm + mt * 16 + (lane >> 2);
                int cl_ = wn + nt * 8 + (lane & 3) * 2;
                float* d = acc[mt][nt];
                *(float2*)(sf + rl_ * RS + cl_)       = make_float2(d[0], d[1]);
                *(float2*)(sf + (rl_ + 8) * RS + cl_) = make_float2(d[2], d[3]);
            }
        }
        __syncthreads();

        const float qscale = 0.08838834764831845f;
        const int q4 = (tid & 15) << 2;
        const int rbase = (tid >> 4) * 8;
        const bool isQ = (n0 < QDIM);
        const bool isK = (n0 >= QDIM) && (n0 < QDIM + KVDIM);

#pragma unroll
        for (int rr = 0; rr < 8; ++rr) {
            int row = rbase + rr;
            int grow = m0 + row;
            const float* bp = sf + row * RS + q4;
            float4 x0 = *(const float4*)bp;
            float4 x1 = *(const float4*)(bp + 64);
            uint2 lo, hi;
            if (isQ || isK) {
                float4 c4 = *(const float4*)(cs_tab + (size_t)grow * 64 + q4);
                float4 s4 = *(const float4*)(sn_tab + (size_t)grow * 64 + q4);
                if (isQ) {
                    lo.x = pack2h((x0.x * c4.x - x1.x * s4.x) * qscale,
                                  (x0.y * c4.y - x1.y * s4.y) * qscale);
                    lo.y = pack2h((x0.z * c4.z - x1.z * s4.z) * qscale,
                                  (x0.w * c4.w - x1.w * s4.w) * qscale);
                    hi.x = pack2h((x1.x * c4.x + x0.x * s4.x) * qscale,
                                  (x1.y * c4.y + x0.y * s4.y) * qscale);
                    hi.y = pack2h((x1.z * c4.z + x0.z * s4.z) * qscale,
                                  (x1.w * c4.w + x0.w * s4.w) * qscale);
                } else {
                    lo.x = pack2h(x0.x * c4.x - x1.x * s4.x, x0.y * c4.y - x1.y * s4.y);
                    lo.y = pack2h(x0.z * c4.z - x1.z * s4.z, x0.w * c4.w - x1.w * s4.w);
                    hi.x = pack2h(x1.x * c4.x + x0.x * s4.x, x1.y * c4.y + x0.y * s4.y);
                    hi.y = pack2h(x1.z * c4.z + x0.z * s4.z, x1.w * c4.w + x0.w * s4.w);
                }
            } else {
                lo.x = pack2h(x0.x, x0.y); lo.y = pack2h(x0.z, x0.w);
                hi.x = pack2h(x1.x, x1.y); hi.y = pack2h(x1.z, x1.w);
            }
            __half* dst;
            if (isQ)      dst = Qh + (size_t)grow * QDIM + n0 + q4;
            else if (isK) dst = Kh + (size_t)grow * KVDIM + (n0 - QDIM) + q4;
            else          dst = Vh + (size_t)grow * KVDIM + (n0 - QDIM - KVDIM) + q4;
            *(uint2*)dst        = lo;
            *(uint2*)(dst + 64) = hi;
        }
    }
}

// ---------------- HMMA flash attention (causal, k-tile 128, 3-stage ring) ----------------
#define ASWZ(row, g) ((row) * 256 + (((g) ^ ((row) & 7)) << 4))

__global__ __launch_bounds__(256) void attn_hmma(
    const __half* __restrict__ Qh, const __half* __restrict__ Kh,
    const __half* __restrict__ Vh, __half* __restrict__ AOh)
{
    extern __shared__ char sm[];
    const uint32_t sb = smem_u32(sm);
    constexpr int MTILE = 128 * 128 * 2;
    constexpr int STAGE = 2 * MTILE;

    const int tid = threadIdx.x, wid = tid >> 5, lane = tid & 31;
    const int h  = blockIdx.y, kh = h >> 2;
    const int bq = gridDim.x - 1 - blockIdx.x;
    const int q0 = bq * 128;
    const int wr = wid * 16;
    const int r  = lane >> 2, c2 = (lane & 3) * 2;
    const int rl = lane & 15, chh = lane >> 4;

    uint32_t qf[8][4];
    {
        const int row0 = q0 + wr + r;
#pragma unroll
        for (int ks = 0; ks < 8; ++ks) {
            int k2 = ks * 16 + c2;
            size_t b00 = (size_t)row0 * QDIM + h * HD + k2;
            size_t b10 = b00 + (size_t)8 * QDIM;
            qf[ks][0] = *(const uint32_t*)(Qh + b00);
            qf[ks][1] = *(const uint32_t*)(Qh + b10);
            qf[ks][2] = *(const uint32_t*)(Qh + b00 + 8);
            qf[ks][3] = *(const uint32_t*)(Qh + b10 + 8);
        }
    }

    float o[16][4];
#pragma unroll
    for (int i = 0; i < 16; ++i)
#pragma unroll
        for (int q = 0; q < 4; ++q) o[i][q] = 0.f;
    float m1 = -1e30f, m2 = -1e30f, l1 = 0.f, l2 = 0.f;

    const int ntiles = bq + 1;

    auto load_kv = [&](int kt, int s) {
        const int k0 = kt * 128;
        const uint32_t st = sb + s * STAGE;
#pragma unroll
        for (int i = 0; i < 8; ++i) {
            int id = tid + i * 256;
            int rw = id >> 4, g = id & 15;
            uint32_t off = ASWZ(rw, g);
            size_t src = (size_t)(k0 + rw) * KVDIM + kh * HD + g * 8;
            cpa16(st + off,         Kh + src);
            cpa16(st + MTILE + off, Vh + src);
        }
        CP_COMMIT();
    };

    load_kv(0, 0);

    int sidx = 0, nsidx = 1;
    for (int kt = 0; kt < ntiles; ++kt) {
        if (kt + 1 < ntiles) {
            load_kv(kt + 1, nsidx);
            nsidx = (nsidx == 2) ? 0 : nsidx + 1;
            CP_WAIT1();
        } else {
            CP_WAIT0();
        }
        __syncthreads();

        const uint32_t st = sb + sidx * STAGE;
        sidx = (sidx == 2) ? 0 : sidx + 1;
        const int k0 = kt * 128;

        float sacc[16][4];
#pragma unroll
        for (int i = 0; i < 16; ++i)
#pragma unroll
            for (int q = 0; q < 4; ++q) sacc[i][q] = 0.f;

#pragma unroll
        for (int ks = 0; ks < 8; ++ks) {
#pragma unroll
            for (int np = 0; np < 8; ++np) {
                uint32_t b0, b1, b2, b3;
                ldsm_x4(b0, b1, b2, b3, st + ASWZ(np * 16 + rl, 2 * ks + chh));
                float* d0 = sacc[np * 2];
                float* d1 = sacc[np * 2 + 1];
                mma_f16(d0[0], d0[1], d0[2], d0[3],
                        qf[ks][0], qf[ks][1], qf[ks][2], qf[ks][3], b0, b2);
                mma_f16(d1[0], d1[1], d1[2], d1[3],
                        qf[ks][0], qf[ks][1], qf[ks][2], qf[ks][3], b1, b3);
            }
        }

        if (k0 + 127 > q0 + wr) {
            const int row1 = q0 + wr + r, row2 = row1 + 8;
#pragma unroll
            for (int nt = 0; nt < 16; ++nt) {
                int col = k0 + nt * 8 + c2;
                if (col     > row1) sacc[nt][0] = -1e30f;
                if (col + 1 > row1) sacc[nt][1] = -1e30f;
                if (col     > row2) sacc[nt][2] = -1e30f;
                if (col + 1 > row2) sacc[nt][3] = -1e30f;
            }
        }

        float mx1 = -1e30f, mx2 = -1e30f;
#pragma unroll
        for (int nt = 0; nt < 16; ++nt) {
            mx1 = fmaxf(mx1, fmaxf(sacc[nt][0], sacc[nt][1]));
            mx2 = fmaxf(mx2, fmaxf(sacc[nt][2], sacc[nt][3]));
        }
        mx1 = fmaxf(mx1, __shfl_xor_sync(0xffffffffu, mx1, 1));
        mx1 = fmaxf(mx1, __shfl_xor_sync(0xffffffffu, mx1, 2));
        mx2 = fmaxf(mx2, __shfl_xor_sync(0xffffffffu, mx2, 1));
        mx2 = fmaxf(mx2, __shfl_xor_sync(0xffffffffu, mx2, 2));
        float nm1 = fmaxf(m1, mx1), nm2 = fmaxf(m2, mx2);
        float cf1 = __expf(m1 - nm1), cf2 = __expf(m2 - nm2);
        m1 = nm1; m2 = nm2;

        float ls1 = 0.f, ls2 = 0.f;
#pragma unroll
        for (int nt = 0; nt < 16; ++nt) {
            sacc[nt][0] = __expf(sacc[nt][0] - nm1);
            sacc[nt][1] = __expf(sacc[nt][1] - nm1);
            sacc[nt][2] = __expf(sacc[nt][2] - nm2);
            sacc[nt][3] = __expf(sacc[nt][3] - nm2);
            ls1 += sacc[nt][0] + sacc[nt][1];
            ls2 += sacc[nt][2] + sacc[nt][3];
        }
        ls1 += __shfl_xor_sync(0xffffffffu, ls1, 1);
        ls1 += __shfl_xor_sync(0xffffffffu, ls1, 2);
        ls2 += __shfl_xor_sync(0xffffffffu, ls2, 1);
        ls2 += __shfl_xor_sync(0xffffffffu, ls2, 2);
        l1 = l1 * cf1 + ls1;
        l2 = l2 * cf2 + ls2;
#pragma unroll
        for (int dt = 0; dt < 16; ++dt) {
            o[dt][0] *= cf1; o[dt][1] *= cf1;
            o[dt][2] *= cf2; o[dt][3] *= cf2;
        }

#pragma unroll
        for (int s = 0; s < 8; ++s) {
            uint32_t ap[4];
#pragma unroll
            for (int half = 0; half < 2; ++half) {
                const float* sv = sacc[2 * s + half];
                ap[2 * half + 0] = pack2h(sv[0], sv[1]);
                ap[2 * half + 1] = pack2h(sv[2], sv[3]);
            }
#pragma unroll
            for (int dg = 0; dg < 8; ++dg) {
                uint32_t v0, v1, v2, v3;
                ldsm_x4_t(v0, v1, v2, v3,
                          st + MTILE + ASWZ(s * 16 + rl, 2 * dg + chh));
                float* d0 = o[2 * dg];
                float* d1 = o[2 * dg + 1];
                mma_f16(d0[0], d0[1], d0[2], d0[3], ap[0], ap[1], ap[2], ap[3], v0, v1);
                mma_f16(d1[0], d1[1], d1[2], d1[3], ap[0], ap[1], ap[2], ap[3], v2, v3);
            }
        }
    }

    const float inv1 = 1.f / l1, inv2 = 1.f / l2;
    const int row1 = q0 + wr + r;
#pragma unroll
    for (int dt = 0; dt < 16; ++dt) {
        size_t c0 = (size_t)row1 * QDIM + h * HD + dt * 8 + c2;
        size_t c1 = c0 + (size_t)8 * QDIM;
        *(uint32_t*)(AOh + c0) = pack2h(o[dt][0] * inv1, o[dt][1] * inv1);
        *(uint32_t*)(AOh + c1) = pack2h(o[dt][2] * inv2, o[dt][3] * inv2);
    }
}

// ---------------- launch ----------------
extern "C" void kernel_launch(void* const* d_in, const int* in_sizes, int n_in,
                              void* d_out, int out_size)
{
    const float* hs   = (const float*)d_in[0];
    const int*   pos  = (const int*)d_in[2];
    const float* Wq   = (const float*)d_in[3];
    const float* Wk   = (const float*)d_in[4];
    const float* Wv   = (const float*)d_in[5];
    const float* Wo   = (const float*)d_in[6];
    float* out = (float*)d_out;

    __half *ah, *aoh, *qhp, *khp, *vhp, *wqkv, *wo16;
    float *csp, *snp;
    cudaGetSymbolAddress((void**)&ah,   g_Ah);
    cudaGetSymbolAddress((void**)&aoh,  g_AOh);
    cudaGetSymbolAddress((void**)&qhp,  g_Qh);
    cudaGetSymbolAddress((void**)&khp,  g_Kh);
    cudaGetSymbolAddress((void**)&vhp,  g_Vh);
    cudaGetSymbolAddress((void**)&wqkv, g_Wqkv);
    cudaGetSymbolAddress((void**)&wo16, g_Wo16);
    cudaGetSymbolAddress((void**)&csp,  g_cs);
    cudaGetSymbolAddress((void**)&snp,  g_sn);

    const int gemm_smem = 3 * (128 * 64 * 2 + 64 * 128 * 2);  // 98304
    cudaFuncSetAttribute(gemm_hmma<0>, cudaFuncAttributeMaxDynamicSharedMemorySize, gemm_smem);
    cudaFuncSetAttribute(gemm_hmma<1>, cudaFuncAttributeMaxDynamicSharedMemorySize, gemm_smem);
    const int attn_smem = 3 * 2 * 128 * 128 * 2;   // 196608
    cudaFuncSetAttribute(attn_hmma, cudaFuncAttributeMaxDynamicSharedMemorySize, attn_smem);

    // all converts + rope table, 4 items/thread (grid fixed: 1024 + 5120 + 128)
    conv_fused<<<6272, 256>>>(hs, Wq, Wk, Wv, Wo, pos, ah, wqkv, wo16, csp, snp);

    // fused QKV projection + RoPE + fp16 epilogue (N=6144)
    gemm_hmma<1><<<dim3(QKVD / 128, SQ / 128), 256, gemm_smem>>>(
        ah, wqkv, nullptr, qhp, khp, vhp, csp, snp, SQ, QKVD, HID);

    // attention (plain fp16 operands, fp32 softmax/accum, k-tile 128)
    attn_hmma<<<dim3(SQ / 128, NH), 256, attn_smem>>>(qhp, khp, vhp, aoh);

    // output projection (plain fp32 epilogue)
    gemm_hmma<0><<<dim3(HID / 128, SQ / 128), 256, gemm_smem>>>(
        aoh, wo16, out, nullptr, nullptr, nullptr, nullptr, nullptr, SQ, HID, QDIM);
}